// round 12
// baseline (speedup 1.0000x reference)
#include <cuda_runtime.h>
#include <cuda_bf16.h>
#include <cstdint>

// ---------------------------------------------------------------------------
// GeneInteractionDango v11: correct v8 dataflow (separate V and O GEMMs,
// per-head attention), Q+K fused A-pass, PERSISTENT blocks (296 = 2/SM,
// each loops ~28 tiles) with cp.async double-buffered Xs prefetch.
// B operands pre-packed as mma fragments in global (LDG from L2, no smem).
// Static relu(X0@Ws+bs) via 3 accumulated hi/lo bf16 passes.
// ---------------------------------------------------------------------------

#define GROUPS   131072
#define SEQ      3
#define H        128
#define GPB      16
#define TPB      48
#define NTHREADS 128
#define NTILES   (GROUPS / GPB)      // 8192
#define NBLOCKS  296                 // 2 per SM, persistent

#define XSTR     132      // f32 row stride (words); row = 528 B
#define RB       272u     // bf16 row stride bytes

// smem byte offsets
#define XS0_OFF  0        // f32 [48][132] = 25344
#define XS1_OFF  25344    // ping-pong buffer
#define AB_OFF   50688    // bf16 [48][136] = 13056
#define QB_OFF   63744
#define KB_OFF   76800
#define VB_OFF   89856
#define WP_OFF   102912   // f32[128]
#define BS_OFF   103424   // f32[128]
#define B_OFF    103936   // f32[1024] biases both layers {q,k,v,o}
#define SC_OFF   108032   // f32[48]
#define SMEM_SZ  108224

typedef unsigned long long u64;

// frag images: 0-7 = {Wq,Wk,Wv,Wo} x layer ; 8 = Ws hi ; 9 = Ws lo
// frag[((img*8 + ks)*16 + j)*32 + lane] = (b0 | b1<<32)
__device__ __align__(16) u64 g_frag[10 * 8 * 16 * 32];

__device__ __forceinline__ void mma_bf16(float* c,
                                         uint32_t a0, uint32_t a1, uint32_t a2, uint32_t a3,
                                         uint32_t b0, uint32_t b1)
{
    asm volatile(
        "mma.sync.aligned.m16n8k16.row.col.f32.bf16.bf16.f32 "
        "{%0,%1,%2,%3}, {%4,%5,%6,%7}, {%8,%9}, {%0,%1,%2,%3};"
        : "+f"(c[0]), "+f"(c[1]), "+f"(c[2]), "+f"(c[3])
        : "r"(a0), "r"(a1), "r"(a2), "r"(a3), "r"(b0), "r"(b1));
}

__device__ __forceinline__ void ldsm_x4(uint32_t& r0, uint32_t& r1, uint32_t& r2, uint32_t& r3,
                                        uint32_t addr)
{
    asm volatile("ldmatrix.sync.aligned.m8n8.x4.shared.b16 {%0,%1,%2,%3}, [%4];"
                 : "=r"(r0), "=r"(r1), "=r"(r2), "=r"(r3) : "r"(addr));
}

__device__ __forceinline__ uint32_t smem_u32(const void* p) {
    uint32_t a;
    asm("{ .reg .u64 t; cvta.to.shared.u64 t, %1; cvt.u32.u64 %0, t; }" : "=r"(a) : "l"(p));
    return a;
}

__device__ __forceinline__ uint32_t bf16x2(float a, float b) {
    __nv_bfloat162 v = __floats2bfloat162_rn(a, b);
    return *(uint32_t*)&v;
}

// [48x128] @ [128x32] per warp: A via ldmatrix, B frags via LDG from L2
__device__ __forceinline__ void gemm3g(uint32_t aBase, uint32_t aoff,
                                       const u64* __restrict__ fb,
                                       float acc[3][4][4])
{
    u64 cur[4];
#pragma unroll
    for (int j = 0; j < 4; j++) cur[j] = __ldg(fb + j * 32);
#pragma unroll
    for (int ks = 0; ks < 8; ks++) {
        uint32_t a[3][4];
#pragma unroll
        for (int s = 0; s < 3; s++)
            ldsm_x4(a[s][0], a[s][1], a[s][2], a[s][3],
                    aBase + (uint32_t)s * (16u * RB) + aoff + (uint32_t)ks * 32u);
        u64 nxt[4];
        if (ks < 7) {
#pragma unroll
            for (int j = 0; j < 4; j++) nxt[j] = __ldg(fb + (ks + 1) * 512 + j * 32);
        }
#pragma unroll
        for (int s = 0; s < 3; s++)
#pragma unroll
            for (int j = 0; j < 4; j++)
                mma_bf16(acc[s][j], a[s][0], a[s][1], a[s][2], a[s][3],
                         (uint32_t)cur[j], (uint32_t)(cur[j] >> 32));
        if (ks < 7) {
#pragma unroll
            for (int j = 0; j < 4; j++) cur[j] = nxt[j];
        }
    }
}

// fused two-B pass: one A-ldmatrix stream feeds two accumulator sets (Q + K)
__device__ __forceinline__ void gemm3g2(uint32_t aBase, uint32_t aoff,
                                        const u64* __restrict__ fb1,
                                        const u64* __restrict__ fb2,
                                        float acc1[3][4][4], float acc2[3][4][4])
{
#pragma unroll
    for (int ks = 0; ks < 8; ks++) {
        u64 c1[4], c2[4];
#pragma unroll
        for (int j = 0; j < 4; j++) {
            c1[j] = __ldg(fb1 + ks * 512 + j * 32);
            c2[j] = __ldg(fb2 + ks * 512 + j * 32);
        }
        uint32_t a[3][4];
#pragma unroll
        for (int s = 0; s < 3; s++)
            ldsm_x4(a[s][0], a[s][1], a[s][2], a[s][3],
                    aBase + (uint32_t)s * (16u * RB) + aoff + (uint32_t)ks * 32u);
#pragma unroll
        for (int s = 0; s < 3; s++)
#pragma unroll
            for (int j = 0; j < 4; j++) {
                mma_bf16(acc1[s][j], a[s][0], a[s][1], a[s][2], a[s][3],
                         (uint32_t)c1[j], (uint32_t)(c1[j] >> 32));
                mma_bf16(acc2[s][j], a[s][0], a[s][1], a[s][2], a[s][3],
                         (uint32_t)c2[j], (uint32_t)(c2[j] >> 32));
            }
    }
}

// dual-A, shared-B (static hi*hi + lo*hi)
__device__ __forceinline__ void gemm3g_dual(uint32_t aBase1, uint32_t aBase2, uint32_t aoff,
                                            const u64* __restrict__ fb,
                                            float acc[3][4][4])
{
#pragma unroll
    for (int ks = 0; ks < 8; ks++) {
        u64 cur[4];
#pragma unroll
        for (int j = 0; j < 4; j++) cur[j] = __ldg(fb + ks * 512 + j * 32);
        uint32_t a1[3][4], a2[3][4];
#pragma unroll
        for (int s = 0; s < 3; s++) {
            ldsm_x4(a1[s][0], a1[s][1], a1[s][2], a1[s][3],
                    aBase1 + (uint32_t)s * (16u * RB) + aoff + (uint32_t)ks * 32u);
            ldsm_x4(a2[s][0], a2[s][1], a2[s][2], a2[s][3],
                    aBase2 + (uint32_t)s * (16u * RB) + aoff + (uint32_t)ks * 32u);
        }
#pragma unroll
        for (int s = 0; s < 3; s++)
#pragma unroll
            for (int j = 0; j < 4; j++) {
                uint32_t b0 = (uint32_t)cur[j], b1 = (uint32_t)(cur[j] >> 32);
                mma_bf16(acc[s][j], a1[s][0], a1[s][1], a1[s][2], a1[s][3], b0, b1);
                mma_bf16(acc[s][j], a2[s][0], a2[s][1], a2[s][2], a2[s][3], b0, b1);
            }
    }
}

__device__ __forceinline__ void zero_acc(float acc[3][4][4]) {
#pragma unroll
    for (int s = 0; s < 3; s++)
#pragma unroll
        for (int j = 0; j < 4; j++)
#pragma unroll
            for (int e = 0; e < 4; e++) acc[s][j][e] = 0.f;
}

__device__ __forceinline__ void build_A(const float* __restrict__ Xs,
                                        unsigned char* __restrict__ smA, int tid)
{
#pragma unroll
    for (int i = 0; i < 24; i++) {
        int p = tid + i * NTHREADS;          // 3072 pairs
        int row = p >> 6, cp = p & 63;
        float2 v = *(const float2*)(Xs + row * XSTR + 2 * cp);
        *(uint32_t*)(smA + (uint32_t)row * RB + (uint32_t)cp * 4u) = bf16x2(v.x, v.y);
    }
}

__device__ __forceinline__ void epi_qkv(const float acc[3][4][4], const float* __restrict__ bias,
                                        unsigned char* __restrict__ dst, int n0, int g, int tg)
{
#pragma unroll
    for (int s = 0; s < 3; s++) {
        int r0 = 16 * s + g;
#pragma unroll
        for (int j = 0; j < 4; j++) {
            int c = n0 + 8 * j + 2 * tg;
            float bv0 = bias[c], bv1 = bias[c + 1];
            *(uint32_t*)(dst + (uint32_t)r0 * RB + 2u * c) =
                bf16x2(acc[s][j][0] + bv0, acc[s][j][1] + bv1);
            *(uint32_t*)(dst + (uint32_t)(r0 + 8) * RB + 2u * c) =
                bf16x2(acc[s][j][2] + bv0, acc[s][j][3] + bv1);
        }
    }
}

// prep: pack 10 weight images into mma-fragment order (verified in v7/v8).
__global__ void dango_prep(const float* __restrict__ Ws,
                           const float* __restrict__ Wq, const float* __restrict__ Wk,
                           const float* __restrict__ Wv, const float* __restrict__ Wo)
{
    int t = blockIdx.x * 256 + threadIdx.x;      // 0..40959
    int img  = t >> 12;
    int r    = t & 4095;
    int ks   = r >> 9;
    int j    = (r >> 5) & 15;
    int lane = r & 31;
    int n  = 8 * j + (lane >> 2);
    int k0 = 16 * ks + 2 * (lane & 3);

    const float* src;
    int lo = 0;
    if (img < 8) {
        int l = img >> 2, m = img & 3;
        src = (m == 0 ? Wq : m == 1 ? Wk : m == 2 ? Wv : Wo) + (size_t)l * H * H;
    } else {
        src = Ws;
        lo = (img == 9);
    }

    float w[4];
    w[0] = __ldg(src + (k0)     * H + n);
    w[1] = __ldg(src + (k0 + 1) * H + n);
    w[2] = __ldg(src + (k0 + 8) * H + n);
    w[3] = __ldg(src + (k0 + 9) * H + n);

    __nv_bfloat16 v[4];
#pragma unroll
    for (int i = 0; i < 4; i++) {
        if (!lo) v[i] = __float2bfloat16(w[i]);
        else {
            __nv_bfloat16 h = __float2bfloat16(w[i]);
            v[i] = __float2bfloat16(w[i] - __bfloat162float(h));
        }
    }
    uint32_t b0, b1;
    { __nv_bfloat162 p = __halves2bfloat162(v[0], v[1]); b0 = *(uint32_t*)&p; }
    { __nv_bfloat162 p = __halves2bfloat162(v[2], v[3]); b1 = *(uint32_t*)&p; }
    g_frag[t] = (u64)b0 | ((u64)b1 << 32);
}

__device__ __forceinline__ void prefetch_tile(const float* __restrict__ X0,
                                              uint32_t dstBase, int tile, int tid)
{
    if (tile < NTILES) {
        const float* src = X0 + (size_t)tile * GPB * SEQ * H;
#pragma unroll
        for (int i = 0; i < 12; i++) {
            int idx = tid + i * NTHREADS;        // 1536 float4
            int row = idx >> 5, c4 = idx & 31;
            uint32_t d = dstBase + (uint32_t)row * 528u + (uint32_t)c4 * 16u;
            asm volatile("cp.async.ca.shared.global [%0], [%1], 16;"
                         :: "r"(d), "l"(src + (size_t)row * H + c4 * 4));
        }
    }
    asm volatile("cp.async.commit_group;" ::: "memory");
}

__global__ __launch_bounds__(NTHREADS, 2)
void dango_mma(const float* __restrict__ X0,
               const float* __restrict__ bs_, const float* __restrict__ bq_,
               const float* __restrict__ bk_, const float* __restrict__ bv_,
               const float* __restrict__ bo_, const float* __restrict__ beta,
               const float* __restrict__ Wp, const float* __restrict__ bp,
               float* __restrict__ out)
{
    extern __shared__ unsigned char sm[];
    float* XsBuf[2] = { (float*)(sm + XS0_OFF), (float*)(sm + XS1_OFF) };
    unsigned char* Ab = sm + AB_OFF;
    unsigned char* Qb = sm + QB_OFF;
    unsigned char* Kb = sm + KB_OFF;
    unsigned char* Vb = sm + VB_OFF;
    float* sWp = (float*)(sm + WP_OFF);
    float* sBs = (float*)(sm + BS_OFF);
    float* sB  = (float*)(sm + B_OFF);
    float* sSc = (float*)(sm + SC_OFF);

    const int tid  = threadIdx.x;
    const int wid  = tid >> 5;
    const int lane = tid & 31;
    const int g    = lane >> 2;
    const int tg   = lane & 3;
    const int n0   = wid * 32;

    const uint32_t smbase = smem_u32(sm);
    const uint32_t aoff   = (uint32_t)(lane & 15) * RB + (uint32_t)(lane >> 4) * 16u;
    const uint32_t AbA = smbase + AB_OFF;
    const uint32_t KbA = smbase + KB_OFF, VbA = smbase + VB_OFF;
    const u64* fwarp = g_frag + wid * 128 + lane;   // + img*4096 + ks*512 + j*32

    // ---- once-per-block consts ----
    if (tid < H) { sWp[tid] = __ldg(Wp + tid); sBs[tid] = __ldg(bs_ + tid); }
#pragma unroll
    for (int i = 0; i < 8; i++) {
        int j = tid + i * NTHREADS;
        int l = j >> 9, m = (j >> 7) & 3, c = j & 127;
        const float* p = (m == 0) ? bq_ : (m == 1) ? bk_ : (m == 2) ? bv_ : bo_;
        sB[j] = __ldg(p + l * H + c);
    }
    const float beta0 = __ldg(beta), beta1 = __ldg(beta + 1);
    const float bpv   = __ldg(bp);

    // prefetch first tile into Xs[0]
    prefetch_tile(X0, smbase + XS0_OFF, blockIdx.x, tid);

    int cur = 0;
    float accA[3][4][4], accB[3][4][4];

    for (int tile = blockIdx.x; tile < NTILES; tile += NBLOCKS, cur ^= 1) {
        const float* Xs = XsBuf[cur];
        const size_t base = (size_t)tile * GPB * SEQ * H;
        const int g0 = tile * GPB;

        asm volatile("cp.async.wait_group 0;" ::: "memory");
        __syncthreads();

        // prefetch next tile into the other buffer
        prefetch_tile(X0, smbase + (cur ? XS0_OFF : XS1_OFF), tile + NBLOCKS, tid);

        if (tid < TPB) sSc[tid] = bpv;

        // ---- attention layers ----
        for (int l = 0; l < 2; l++) {
            build_A(Xs, Ab, tid);
            __syncthreads();
            const float* bias = sB + l * 512;

            // fused Q+K pass, then V — sync-free between them
            zero_acc(accA); zero_acc(accB);
            gemm3g2(AbA, aoff, fwarp + (l * 4 + 0) * 4096, fwarp + (l * 4 + 1) * 4096,
                    accA, accB);
            epi_qkv(accA, bias + 0,   Qb, n0, g, tg);
            epi_qkv(accB, bias + 128, Kb, n0, g, tg);

            zero_acc(accA);
            gemm3g(AbA, aoff, fwarp + (l * 4 + 2) * 4096, accA);
            epi_qkv(accA, bias + 256, Vb, n0, g, tg);
            __syncthreads();

            // attention (exclude-self softmax, per-head) -> Ab
            if (tid < GPB * 4) {
                const int grp = tid >> 2, h = tid & 3;
                const int rb = grp * SEQ, ho = h * 32;
                const float inv = 0.17677669529663687f;   // 1/sqrt(32)
#pragma unroll
                for (int qi = 0; qi < SEQ; qi++) {
                    const int k0 = (qi == 0) ? 1 : 0;
                    const int k1 = (qi == 2) ? 1 : 2;
                    const __nv_bfloat162* q  = (const __nv_bfloat162*)(Qb + (uint32_t)(rb + qi) * RB + 2u * ho);
                    const __nv_bfloat162* ka = (const __nv_bfloat162*)(Kb + (uint32_t)(rb + k0) * RB + 2u * ho);
                    const __nv_bfloat162* kb = (const __nv_bfloat162*)(Kb + (uint32_t)(rb + k1) * RB + 2u * ho);
                    float s0 = 0.f, s1 = 0.f;
#pragma unroll
                    for (int d = 0; d < 16; d++) {
                        float2 qv = __bfloat1622float2(q[d]);
                        float2 va = __bfloat1622float2(ka[d]);
                        float2 vb = __bfloat1622float2(kb[d]);
                        s0 += qv.x * va.x + qv.y * va.y;
                        s1 += qv.x * vb.x + qv.y * vb.y;
                    }
                    s0 *= inv; s1 *= inv;
                    float mx = fmaxf(s0, s1);
                    float e0 = expf(s0 - mx), e1 = expf(s1 - mx);
                    float rr = 1.0f / (e0 + e1);
                    float w0 = e0 * rr, w1 = e1 * rr;
                    const __nv_bfloat162* v0 = (const __nv_bfloat162*)(Vb + (uint32_t)(rb + k0) * RB + 2u * ho);
                    const __nv_bfloat162* v1 = (const __nv_bfloat162*)(Vb + (uint32_t)(rb + k1) * RB + 2u * ho);
#pragma unroll
                    for (int d = 0; d < 16; d++) {
                        float2 a = __bfloat1622float2(v0[d]);
                        float2 b = __bfloat1622float2(v1[d]);
                        *(uint32_t*)(Ab + (uint32_t)(rb + qi) * RB + 2u * (ho + 2 * d)) =
                            bf16x2(w0 * a.x + w1 * b.x, w0 * a.y + w1 * b.y);
                    }
                }
            }
            __syncthreads();

            // O gemm + ReZero residual into Xs
            zero_acc(accA);
            gemm3g(AbA, aoff, fwarp + (l * 4 + 3) * 4096, accA);
            {
                const float betaL = (l == 0) ? beta0 : beta1;
                const float* bo = bias + 384;
                float* Xw = XsBuf[cur];
#pragma unroll
                for (int s = 0; s < 3; s++) {
                    int r0 = 16 * s + g;
#pragma unroll
                    for (int j = 0; j < 4; j++) {
                        int c = n0 + 8 * j + 2 * tg;
                        float bv0 = bo[c], bv1 = bo[c + 1];
                        float2* p0 = (float2*)(Xw + r0 * XSTR + c);
                        float2* p1 = (float2*)(Xw + (r0 + 8) * XSTR + c);
                        float2 x0 = *p0, x1 = *p1;
                        x0.x += betaL * (accA[s][j][0] + bv0);
                        x0.y += betaL * (accA[s][j][1] + bv1);
                        x1.x += betaL * (accA[s][j][2] + bv0);
                        x1.y += betaL * (accA[s][j][3] + bv1);
                        *p0 = x0; *p1 = x1;
                    }
                }
            }
            __syncthreads();
        }

        // ---- static path: relu(X0 @ Ws + bs), hi/lo split ----
#pragma unroll
        for (int i = 0; i < 24; i++) {
            int p = tid + i * NTHREADS;
            int row = p >> 6, cp = p & 63;
            float2 v = __ldg((const float2*)(X0 + base + (size_t)row * H + 2 * cp));
            __nv_bfloat16 h0 = __float2bfloat16(v.x), h1 = __float2bfloat16(v.y);
            float r0 = v.x - __bfloat162float(h0), r1 = v.y - __bfloat162float(h1);
            uint32_t off = (uint32_t)row * RB + (uint32_t)cp * 4u;
            __nv_bfloat162 hv = __halves2bfloat162(h0, h1);
            *(uint32_t*)(Kb + off) = *(uint32_t*)&hv;       // A_hi
            *(uint32_t*)(Vb + off) = bf16x2(r0, r1);        // A_lo
        }
        __syncthreads();

        zero_acc(accA);
        gemm3g_dual(KbA, VbA, aoff, fwarp + 8 * 4096, accA);   // hi*hi + lo*hi
        gemm3g(KbA, aoff, fwarp + 9 * 4096, accA);             // hi*lo

        // score epilogue
#pragma unroll
        for (int s = 0; s < 3; s++) {
            int r0 = 16 * s + g;
            float sa = 0.f, sb2 = 0.f;
#pragma unroll
            for (int j = 0; j < 4; j++) {
                int c = n0 + 8 * j + 2 * tg;
                float st, d;
                st = fmaxf(accA[s][j][0] + sBs[c], 0.f);     d = Xs[r0 * XSTR + c] - st;           sa  += d * d * sWp[c];
                st = fmaxf(accA[s][j][1] + sBs[c + 1], 0.f); d = Xs[r0 * XSTR + c + 1] - st;       sa  += d * d * sWp[c + 1];
                st = fmaxf(accA[s][j][2] + sBs[c], 0.f);     d = Xs[(r0 + 8) * XSTR + c] - st;     sb2 += d * d * sWp[c];
                st = fmaxf(accA[s][j][3] + sBs[c + 1], 0.f); d = Xs[(r0 + 8) * XSTR + c + 1] - st; sb2 += d * d * sWp[c + 1];
            }
            sa  += __shfl_xor_sync(0xffffffffu, sa, 1);
            sa  += __shfl_xor_sync(0xffffffffu, sa, 2);
            sb2 += __shfl_xor_sync(0xffffffffu, sb2, 1);
            sb2 += __shfl_xor_sync(0xffffffffu, sb2, 2);
            if (tg == 0) {
                atomicAdd(&sSc[r0], sa);
                atomicAdd(&sSc[r0 + 8], sb2);
            }
        }
        __syncthreads();

        if (tid < GPB)
            out[g0 + tid] = (sSc[tid * 3] + sSc[tid * 3 + 1] + sSc[tid * 3 + 2]) * (1.0f / 3.0f);
    }
}

extern "C" void kernel_launch(void* const* d_in, const int* in_sizes, int n_in,
                              void* d_out, int out_size)
{
    const float* X0  = (const float*)d_in[0];
    // d_in[1] = batch (int64) — implicit: repeat(arange(G), 3)
    const float* Ws  = (const float*)d_in[2];
    const float* bs  = (const float*)d_in[3];
    const float* Wq  = (const float*)d_in[4];
    const float* bq  = (const float*)d_in[5];
    const float* Wk  = (const float*)d_in[6];
    const float* bk  = (const float*)d_in[7];
    const float* Wv  = (const float*)d_in[8];
    const float* bv  = (const float*)d_in[9];
    const float* Wo  = (const float*)d_in[10];
    const float* bo  = (const float*)d_in[11];
    const float* bet = (const float*)d_in[12];
    const float* Wp  = (const float*)d_in[13];
    const float* bp  = (const float*)d_in[14];
    float* out = (float*)d_out;

    dango_prep<<<160, 256>>>(Ws, Wq, Wk, Wv, Wo);

    cudaFuncSetAttribute(dango_mma, cudaFuncAttributeMaxDynamicSharedMemorySize, SMEM_SZ);
    dango_mma<<<NBLOCKS, NTHREADS, SMEM_SZ>>>(
        X0, bs, bq, bk, bv, bo, bet, Wp, bp, out);
}

// round 13
// speedup vs baseline: 1.0002x; 1.0002x over previous
#include <cuda_runtime.h>
#include <cuda_bf16.h>
#include <cstdint>

// ---------------------------------------------------------------------------
// GeneInteractionDango v12: v8 dataflow (best: 505us) + register-resident A
// fragments. Per layer, each warp ldmatrixes the A image ONCE into 96 regs,
// then runs Q, K, V as three register-A GEMMs (B frags streamed from L2).
// O pass and static hi/lo passes stream A as before. Non-persistent grid.
// ---------------------------------------------------------------------------

#define GROUPS   131072
#define SEQ      3
#define H        128
#define GPB      16
#define TPB      48
#define NTHREADS 128

#define XSTR     132      // f32 row stride (words)
#define RB       272u     // bf16 row stride bytes

// smem byte offsets
#define XS_OFF   0        // f32 [48][132] = 25344
#define AB_OFF   25344    // bf16 [48][136] = 13056
#define QB_OFF   38400
#define KB_OFF   51456
#define VB_OFF   64512
#define WP_OFF   77568    // f32[128]
#define BS_OFF   78080    // f32[128]
#define B_OFF    78592    // f32[1024] biases both layers {q,k,v,o}
#define SC_OFF   82688    // f32[48]
#define SMEM_SZ  82880

typedef unsigned long long u64;

// frag images: 0-7 = {Wq,Wk,Wv,Wo} x layer ; 8 = Ws hi ; 9 = Ws lo
// frag[((img*8 + ks)*16 + j)*32 + lane] = (b0 | b1<<32)
__device__ __align__(16) u64 g_frag[10 * 8 * 16 * 32];

__device__ __forceinline__ void mma_bf16(float* c,
                                         uint32_t a0, uint32_t a1, uint32_t a2, uint32_t a3,
                                         uint32_t b0, uint32_t b1)
{
    asm volatile(
        "mma.sync.aligned.m16n8k16.row.col.f32.bf16.bf16.f32 "
        "{%0,%1,%2,%3}, {%4,%5,%6,%7}, {%8,%9}, {%0,%1,%2,%3};"
        : "+f"(c[0]), "+f"(c[1]), "+f"(c[2]), "+f"(c[3])
        : "r"(a0), "r"(a1), "r"(a2), "r"(a3), "r"(b0), "r"(b1));
}

__device__ __forceinline__ void ldsm_x4(uint32_t& r0, uint32_t& r1, uint32_t& r2, uint32_t& r3,
                                        uint32_t addr)
{
    asm volatile("ldmatrix.sync.aligned.m8n8.x4.shared.b16 {%0,%1,%2,%3}, [%4];"
                 : "=r"(r0), "=r"(r1), "=r"(r2), "=r"(r3) : "r"(addr));
}

__device__ __forceinline__ uint32_t smem_u32(const void* p) {
    uint32_t a;
    asm("{ .reg .u64 t; cvta.to.shared.u64 t, %1; cvt.u32.u64 %0, t; }" : "=r"(a) : "l"(p));
    return a;
}

__device__ __forceinline__ uint32_t bf16x2(float a, float b) {
    __nv_bfloat162 v = __floats2bfloat162_rn(a, b);
    return *(uint32_t*)&v;
}

// load all A fragments of the [48x128] tile into registers (96 x u32)
__device__ __forceinline__ void load_afrags(uint32_t aBase, uint32_t aoff, uint32_t af[96])
{
#pragma unroll
    for (int ks = 0; ks < 8; ks++)
#pragma unroll
        for (int s = 0; s < 3; s++)
            ldsm_x4(af[ks * 12 + s * 4 + 0], af[ks * 12 + s * 4 + 1],
                    af[ks * 12 + s * 4 + 2], af[ks * 12 + s * 4 + 3],
                    aBase + (uint32_t)s * (16u * RB) + aoff + (uint32_t)ks * 32u);
}

// GEMM with register-resident A; B frags streamed (prefetch 1 ks ahead)
__device__ __forceinline__ void gemm_reg(const uint32_t af[96],
                                         const u64* __restrict__ fb,
                                         float acc[3][4][4])
{
    u64 cur[4];
#pragma unroll
    for (int j = 0; j < 4; j++) cur[j] = __ldg(fb + j * 32);
#pragma unroll
    for (int ks = 0; ks < 8; ks++) {
        u64 nxt[4];
        if (ks < 7) {
#pragma unroll
            for (int j = 0; j < 4; j++) nxt[j] = __ldg(fb + (ks + 1) * 512 + j * 32);
        }
#pragma unroll
        for (int s = 0; s < 3; s++)
#pragma unroll
            for (int j = 0; j < 4; j++)
                mma_bf16(acc[s][j],
                         af[ks * 12 + s * 4 + 0], af[ks * 12 + s * 4 + 1],
                         af[ks * 12 + s * 4 + 2], af[ks * 12 + s * 4 + 3],
                         (uint32_t)cur[j], (uint32_t)(cur[j] >> 32));
        if (ks < 7) {
#pragma unroll
            for (int j = 0; j < 4; j++) cur[j] = nxt[j];
        }
    }
}

// streaming-A GEMM (O pass): A via ldmatrix, B frags via LDG
__device__ __forceinline__ void gemm3g(uint32_t aBase, uint32_t aoff,
                                       const u64* __restrict__ fb,
                                       float acc[3][4][4])
{
    u64 cur[4];
#pragma unroll
    for (int j = 0; j < 4; j++) cur[j] = __ldg(fb + j * 32);
#pragma unroll
    for (int ks = 0; ks < 8; ks++) {
        uint32_t a[3][4];
#pragma unroll
        for (int s = 0; s < 3; s++)
            ldsm_x4(a[s][0], a[s][1], a[s][2], a[s][3],
                    aBase + (uint32_t)s * (16u * RB) + aoff + (uint32_t)ks * 32u);
        u64 nxt[4];
        if (ks < 7) {
#pragma unroll
            for (int j = 0; j < 4; j++) nxt[j] = __ldg(fb + (ks + 1) * 512 + j * 32);
        }
#pragma unroll
        for (int s = 0; s < 3; s++)
#pragma unroll
            for (int j = 0; j < 4; j++)
                mma_bf16(acc[s][j], a[s][0], a[s][1], a[s][2], a[s][3],
                         (uint32_t)cur[j], (uint32_t)(cur[j] >> 32));
        if (ks < 7) {
#pragma unroll
            for (int j = 0; j < 4; j++) cur[j] = nxt[j];
        }
    }
}

// dual-A, shared-B (static hi*hi + lo*hi)
__device__ __forceinline__ void gemm3g_dual(uint32_t aBase1, uint32_t aBase2, uint32_t aoff,
                                            const u64* __restrict__ fb,
                                            float acc[3][4][4])
{
#pragma unroll
    for (int ks = 0; ks < 8; ks++) {
        u64 cur[4];
#pragma unroll
        for (int j = 0; j < 4; j++) cur[j] = __ldg(fb + ks * 512 + j * 32);
        uint32_t a1[3][4], a2[3][4];
#pragma unroll
        for (int s = 0; s < 3; s++) {
            ldsm_x4(a1[s][0], a1[s][1], a1[s][2], a1[s][3],
                    aBase1 + (uint32_t)s * (16u * RB) + aoff + (uint32_t)ks * 32u);
            ldsm_x4(a2[s][0], a2[s][1], a2[s][2], a2[s][3],
                    aBase2 + (uint32_t)s * (16u * RB) + aoff + (uint32_t)ks * 32u);
        }
#pragma unroll
        for (int s = 0; s < 3; s++)
#pragma unroll
            for (int j = 0; j < 4; j++) {
                uint32_t b0 = (uint32_t)cur[j], b1 = (uint32_t)(cur[j] >> 32);
                mma_bf16(acc[s][j], a1[s][0], a1[s][1], a1[s][2], a1[s][3], b0, b1);
                mma_bf16(acc[s][j], a2[s][0], a2[s][1], a2[s][2], a2[s][3], b0, b1);
            }
    }
}

__device__ __forceinline__ void zero_acc(float acc[3][4][4]) {
#pragma unroll
    for (int s = 0; s < 3; s++)
#pragma unroll
        for (int j = 0; j < 4; j++)
#pragma unroll
            for (int e = 0; e < 4; e++) acc[s][j][e] = 0.f;
}

__device__ __forceinline__ void build_A(const float* __restrict__ Xs,
                                        unsigned char* __restrict__ smA, int tid)
{
#pragma unroll
    for (int i = 0; i < 24; i++) {
        int p = tid + i * NTHREADS;
        int row = p >> 6, cp = p & 63;
        float2 v = *(const float2*)(Xs + row * XSTR + 2 * cp);
        *(uint32_t*)(smA + (uint32_t)row * RB + (uint32_t)cp * 4u) = bf16x2(v.x, v.y);
    }
}

__device__ __forceinline__ void epi_qkv(const float acc[3][4][4], const float* __restrict__ bias,
                                        unsigned char* __restrict__ dst, int n0, int g, int tg)
{
#pragma unroll
    for (int s = 0; s < 3; s++) {
        int r0 = 16 * s + g;
#pragma unroll
        for (int j = 0; j < 4; j++) {
            int c = n0 + 8 * j + 2 * tg;
            float bv0 = bias[c], bv1 = bias[c + 1];
            *(uint32_t*)(dst + (uint32_t)r0 * RB + 2u * c) =
                bf16x2(acc[s][j][0] + bv0, acc[s][j][1] + bv1);
            *(uint32_t*)(dst + (uint32_t)(r0 + 8) * RB + 2u * c) =
                bf16x2(acc[s][j][2] + bv0, acc[s][j][3] + bv1);
        }
    }
}

// prep: pack 10 weight images into mma-fragment order (verified v7/v8).
__global__ void dango_prep(const float* __restrict__ Ws,
                           const float* __restrict__ Wq, const float* __restrict__ Wk,
                           const float* __restrict__ Wv, const float* __restrict__ Wo)
{
    int t = blockIdx.x * 256 + threadIdx.x;      // 0..40959
    int img  = t >> 12;
    int r    = t & 4095;
    int ks   = r >> 9;
    int j    = (r >> 5) & 15;
    int lane = r & 31;
    int n  = 8 * j + (lane >> 2);
    int k0 = 16 * ks + 2 * (lane & 3);

    const float* src;
    int lo = 0;
    if (img < 8) {
        int l = img >> 2, m = img & 3;
        src = (m == 0 ? Wq : m == 1 ? Wk : m == 2 ? Wv : Wo) + (size_t)l * H * H;
    } else {
        src = Ws;
        lo = (img == 9);
    }

    float w[4];
    w[0] = __ldg(src + (k0)     * H + n);
    w[1] = __ldg(src + (k0 + 1) * H + n);
    w[2] = __ldg(src + (k0 + 8) * H + n);
    w[3] = __ldg(src + (k0 + 9) * H + n);

    __nv_bfloat16 v[4];
#pragma unroll
    for (int i = 0; i < 4; i++) {
        if (!lo) v[i] = __float2bfloat16(w[i]);
        else {
            __nv_bfloat16 h = __float2bfloat16(w[i]);
            v[i] = __float2bfloat16(w[i] - __bfloat162float(h));
        }
    }
    uint32_t b0, b1;
    { __nv_bfloat162 p = __halves2bfloat162(v[0], v[1]); b0 = *(uint32_t*)&p; }
    { __nv_bfloat162 p = __halves2bfloat162(v[2], v[3]); b1 = *(uint32_t*)&p; }
    g_frag[t] = (u64)b0 | ((u64)b1 << 32);
}

__global__ __launch_bounds__(NTHREADS, 2)
void dango_mma(const float* __restrict__ X0,
               const float* __restrict__ bs_, const float* __restrict__ bq_,
               const float* __restrict__ bk_, const float* __restrict__ bv_,
               const float* __restrict__ bo_, const float* __restrict__ beta,
               const float* __restrict__ Wp, const float* __restrict__ bp,
               float* __restrict__ out)
{
    extern __shared__ unsigned char sm[];
    float*         Xs = (float*)(sm + XS_OFF);
    unsigned char* Ab = sm + AB_OFF;
    unsigned char* Qb = sm + QB_OFF;
    unsigned char* Kb = sm + KB_OFF;
    unsigned char* Vb = sm + VB_OFF;
    float* sWp = (float*)(sm + WP_OFF);
    float* sBs = (float*)(sm + BS_OFF);
    float* sB  = (float*)(sm + B_OFF);
    float* sSc = (float*)(sm + SC_OFF);

    const int tid  = threadIdx.x;
    const int wid  = tid >> 5;
    const int lane = tid & 31;
    const int g    = lane >> 2;
    const int tg   = lane & 3;
    const int n0   = wid * 32;
    const int g0   = blockIdx.x * GPB;
    const size_t base = (size_t)g0 * SEQ * H;

    const uint32_t smbase = smem_u32(sm);
    const uint32_t aoff   = (uint32_t)(lane & 15) * RB + (uint32_t)(lane >> 4) * 16u;
    const uint32_t AbA = smbase + AB_OFF;
    const uint32_t KbA = smbase + KB_OFF, VbA = smbase + VB_OFF;
    const u64* fwarp = g_frag + wid * 128 + lane;   // + img*4096 + ks*512 + j*32

    // ---- init: Xs, consts ----
    for (int i = 0; i < 12; i++) {
        int idx = tid + i * NTHREADS;        // 1536 float4
        int row = idx >> 5, c4 = idx & 31;
        float4 v = __ldg((const float4*)(X0 + base + (size_t)row * H + c4 * 4));
        *(float4*)(Xs + row * XSTR + c4 * 4) = v;
    }
    if (tid < H) { sWp[tid] = __ldg(Wp + tid); sBs[tid] = __ldg(bs_ + tid); }
#pragma unroll
    for (int i = 0; i < 8; i++) {
        int j = tid + i * NTHREADS;
        int l = j >> 9, m = (j >> 7) & 3, c = j & 127;
        const float* p = (m == 0) ? bq_ : (m == 1) ? bk_ : (m == 2) ? bv_ : bo_;
        sB[j] = __ldg(p + l * H + c);
    }
    if (tid < TPB) sSc[tid] = __ldg(bp);
    __syncthreads();

    float acc[3][4][4];

    // ---- attention layers ----
    for (int l = 0; l < 2; l++) {
        build_A(Xs, Ab, tid);
        __syncthreads();
        const float* bias = sB + l * 512;

        // A fragments once per layer -> registers
        uint32_t af[96];
        load_afrags(AbA, aoff, af);

        // Q, K, V as register-A GEMMs, sync-free between them
        zero_acc(acc);
        gemm_reg(af, fwarp + (l * 4 + 0) * 4096, acc);
        epi_qkv(acc, bias + 0, Qb, n0, g, tg);

        zero_acc(acc);
        gemm_reg(af, fwarp + (l * 4 + 1) * 4096, acc);
        epi_qkv(acc, bias + 128, Kb, n0, g, tg);

        zero_acc(acc);
        gemm_reg(af, fwarp + (l * 4 + 2) * 4096, acc);
        epi_qkv(acc, bias + 256, Vb, n0, g, tg);
        __syncthreads();

        // attention (exclude-self softmax, per-head) -> Ab
        if (tid < GPB * 4) {
            const int grp = tid >> 2, h = tid & 3;
            const int rb = grp * SEQ, ho = h * 32;
            const float inv = 0.17677669529663687f;   // 1/sqrt(32)
#pragma unroll
            for (int qi = 0; qi < SEQ; qi++) {
                const int k0 = (qi == 0) ? 1 : 0;
                const int k1 = (qi == 2) ? 1 : 2;
                const __nv_bfloat162* q  = (const __nv_bfloat162*)(Qb + (uint32_t)(rb + qi) * RB + 2u * ho);
                const __nv_bfloat162* ka = (const __nv_bfloat162*)(Kb + (uint32_t)(rb + k0) * RB + 2u * ho);
                const __nv_bfloat162* kb = (const __nv_bfloat162*)(Kb + (uint32_t)(rb + k1) * RB + 2u * ho);
                float s0 = 0.f, s1 = 0.f;
#pragma unroll
                for (int d = 0; d < 16; d++) {
                    float2 qv = __bfloat1622float2(q[d]);
                    float2 va = __bfloat1622float2(ka[d]);
                    float2 vb = __bfloat1622float2(kb[d]);
                    s0 += qv.x * va.x + qv.y * va.y;
                    s1 += qv.x * vb.x + qv.y * vb.y;
                }
                s0 *= inv; s1 *= inv;
                float mx = fmaxf(s0, s1);
                float e0 = expf(s0 - mx), e1 = expf(s1 - mx);
                float rr = 1.0f / (e0 + e1);
                float w0 = e0 * rr, w1 = e1 * rr;
                const __nv_bfloat162* v0 = (const __nv_bfloat162*)(Vb + (uint32_t)(rb + k0) * RB + 2u * ho);
                const __nv_bfloat162* v1 = (const __nv_bfloat162*)(Vb + (uint32_t)(rb + k1) * RB + 2u * ho);
#pragma unroll
                for (int d = 0; d < 16; d++) {
                    float2 a = __bfloat1622float2(v0[d]);
                    float2 b = __bfloat1622float2(v1[d]);
                    *(uint32_t*)(Ab + (uint32_t)(rb + qi) * RB + 2u * (ho + 2 * d)) =
                        bf16x2(w0 * a.x + w1 * b.x, w0 * a.y + w1 * b.y);
                }
            }
        }
        __syncthreads();

        // O gemm (streaming A from Ab) + ReZero residual into Xs
        zero_acc(acc);
        gemm3g(AbA, aoff, fwarp + (l * 4 + 3) * 4096, acc);
        {
            const float betaL = __ldg(beta + l);
            const float* bo = bias + 384;
#pragma unroll
            for (int s = 0; s < 3; s++) {
                int r0 = 16 * s + g;
#pragma unroll
                for (int j = 0; j < 4; j++) {
                    int c = n0 + 8 * j + 2 * tg;
                    float bv0 = bo[c], bv1 = bo[c + 1];
                    float2* p0 = (float2*)(Xs + r0 * XSTR + c);
                    float2* p1 = (float2*)(Xs + (r0 + 8) * XSTR + c);
                    float2 x0 = *p0, x1 = *p1;
                    x0.x += betaL * (acc[s][j][0] + bv0);
                    x0.y += betaL * (acc[s][j][1] + bv1);
                    x1.x += betaL * (acc[s][j][2] + bv0);
                    x1.y += betaL * (acc[s][j][3] + bv1);
                    *p0 = x0; *p1 = x1;
                }
            }
        }
        __syncthreads();
    }

    // ---- static path: relu(X0 @ Ws + bs), hi/lo split ----
#pragma unroll
    for (int i = 0; i < 24; i++) {
        int p = tid + i * NTHREADS;
        int row = p >> 6, cp = p & 63;
        float2 v = __ldg((const float2*)(X0 + base + (size_t)row * H + 2 * cp));
        __nv_bfloat16 h0 = __float2bfloat16(v.x), h1 = __float2bfloat16(v.y);
        float r0 = v.x - __bfloat162float(h0), r1 = v.y - __bfloat162float(h1);
        uint32_t off = (uint32_t)row * RB + (uint32_t)cp * 4u;
        __nv_bfloat162 hv = __halves2bfloat162(h0, h1);
        *(uint32_t*)(Kb + off) = *(uint32_t*)&hv;       // A_hi
        *(uint32_t*)(Vb + off) = bf16x2(r0, r1);        // A_lo
    }
    __syncthreads();

    zero_acc(acc);
    gemm3g_dual(KbA, VbA, aoff, fwarp + 8 * 4096, acc);   // hi*hi + lo*hi
    gemm3g(KbA, aoff, fwarp + 9 * 4096, acc);             // hi*lo

    // score epilogue
#pragma unroll
    for (int s = 0; s < 3; s++) {
        int r0 = 16 * s + g;
        float sa = 0.f, sb2 = 0.f;
#pragma unroll
        for (int j = 0; j < 4; j++) {
            int c = n0 + 8 * j + 2 * tg;
            float st, d;
            st = fmaxf(acc[s][j][0] + sBs[c], 0.f);     d = Xs[r0 * XSTR + c] - st;           sa  += d * d * sWp[c];
            st = fmaxf(acc[s][j][1] + sBs[c + 1], 0.f); d = Xs[r0 * XSTR + c + 1] - st;       sa  += d * d * sWp[c + 1];
            st = fmaxf(acc[s][j][2] + sBs[c], 0.f);     d = Xs[(r0 + 8) * XSTR + c] - st;     sb2 += d * d * sWp[c];
            st = fmaxf(acc[s][j][3] + sBs[c + 1], 0.f); d = Xs[(r0 + 8) * XSTR + c + 1] - st; sb2 += d * d * sWp[c + 1];
        }
        sa  += __shfl_xor_sync(0xffffffffu, sa, 1);
        sa  += __shfl_xor_sync(0xffffffffu, sa, 2);
        sb2 += __shfl_xor_sync(0xffffffffu, sb2, 1);
        sb2 += __shfl_xor_sync(0xffffffffu, sb2, 2);
        if (tg == 0) {
            atomicAdd(&sSc[r0], sa);
            atomicAdd(&sSc[r0 + 8], sb2);
        }
    }
    __syncthreads();

    if (tid < GPB)
        out[g0 + tid] = (sSc[tid * 3] + sSc[tid * 3 + 1] + sSc[tid * 3 + 2]) * (1.0f / 3.0f);
}

extern "C" void kernel_launch(void* const* d_in, const int* in_sizes, int n_in,
                              void* d_out, int out_size)
{
    const float* X0  = (const float*)d_in[0];
    // d_in[1] = batch (int64) — implicit: repeat(arange(G), 3)
    const float* Ws  = (const float*)d_in[2];
    const float* bs  = (const float*)d_in[3];
    const float* Wq  = (const float*)d_in[4];
    const float* bq  = (const float*)d_in[5];
    const float* Wk  = (const float*)d_in[6];
    const float* bk  = (const float*)d_in[7];
    const float* Wv  = (const float*)d_in[8];
    const float* bv  = (const float*)d_in[9];
    const float* Wo  = (const float*)d_in[10];
    const float* bo  = (const float*)d_in[11];
    const float* bet = (const float*)d_in[12];
    const float* Wp  = (const float*)d_in[13];
    const float* bp  = (const float*)d_in[14];
    float* out = (float*)d_out;

    dango_prep<<<160, 256>>>(Ws, Wq, Wk, Wv, Wo);

    cudaFuncSetAttribute(dango_mma, cudaFuncAttributeMaxDynamicSharedMemorySize, SMEM_SZ);
    dango_mma<<<GROUPS / GPB, NTHREADS, SMEM_SZ>>>(
        X0, bs, bq, bk, bv, bo, bet, Wp, bp, out);
}

// round 14
// speedup vs baseline: 1.1156x; 1.1154x over previous
#include <cuda_runtime.h>
#include <cuda_bf16.h>
#include <cstdint>

// ---------------------------------------------------------------------------
// GeneInteractionDango v13: v8 dataflow (best known: 505us) slimmed to fit
// THREE blocks per SM (12 warps/SM): smem 76800B (biases via __ldg, sSc
// overlaid on Xs, Qb stride-256 row-swizzled), __launch_bounds__(128,3).
// Per-work L1 traffic identical to v8; concurrency x1.5.
// ---------------------------------------------------------------------------

#define GROUPS   131072
#define SEQ      3
#define H        128
#define GPB      16
#define TPB      48
#define NTHREADS 128

#define XSTR     132      // f32 row stride (words)
#define RB       272u     // bf16 row stride bytes (ldsm-safe)
#define QRB      256u     // Qb row stride bytes (swizzled, non-ldsm)

// smem byte offsets (total 76800)
#define XS_OFF   0        // f32 [48][132] = 25344 (tail reused as sSc)
#define AB_OFF   25344    // bf16 [48][136] = 13056
#define KB_OFF   38400
#define VB_OFF   51456
#define QB_OFF   64512    // bf16 [48][128] swizzled = 12288
#define SMEM_SZ  76800

typedef unsigned long long u64;

// frag images: 0-7 = {Wq,Wk,Wv,Wo} x layer ; 8 = Ws hi ; 9 = Ws lo
__device__ __align__(16) u64 g_frag[10 * 8 * 16 * 32];

__device__ __forceinline__ void mma_bf16(float* c,
                                         uint32_t a0, uint32_t a1, uint32_t a2, uint32_t a3,
                                         uint32_t b0, uint32_t b1)
{
    asm volatile(
        "mma.sync.aligned.m16n8k16.row.col.f32.bf16.bf16.f32 "
        "{%0,%1,%2,%3}, {%4,%5,%6,%7}, {%8,%9}, {%0,%1,%2,%3};"
        : "+f"(c[0]), "+f"(c[1]), "+f"(c[2]), "+f"(c[3])
        : "r"(a0), "r"(a1), "r"(a2), "r"(a3), "r"(b0), "r"(b1));
}

__device__ __forceinline__ void ldsm_x4(uint32_t& r0, uint32_t& r1, uint32_t& r2, uint32_t& r3,
                                        uint32_t addr)
{
    asm volatile("ldmatrix.sync.aligned.m8n8.x4.shared.b16 {%0,%1,%2,%3}, [%4];"
                 : "=r"(r0), "=r"(r1), "=r"(r2), "=r"(r3) : "r"(addr));
}

__device__ __forceinline__ uint32_t smem_u32(const void* p) {
    uint32_t a;
    asm("{ .reg .u64 t; cvta.to.shared.u64 t, %1; cvt.u32.u64 %0, t; }" : "=r"(a) : "l"(p));
    return a;
}

__device__ __forceinline__ uint32_t bf16x2(float a, float b) {
    __nv_bfloat162 v = __floats2bfloat162_rn(a, b);
    return *(uint32_t*)&v;
}

// streaming-A GEMM: [48x128]@[128x32] per warp; A via ldmatrix, B via LDG
__device__ __forceinline__ void gemm3g(uint32_t aBase, uint32_t aoff,
                                       const u64* __restrict__ fb,
                                       float acc[3][4][4])
{
    u64 cur[4];
#pragma unroll
    for (int j = 0; j < 4; j++) cur[j] = __ldg(fb + j * 32);
#pragma unroll
    for (int ks = 0; ks < 8; ks++) {
        uint32_t a[3][4];
#pragma unroll
        for (int s = 0; s < 3; s++)
            ldsm_x4(a[s][0], a[s][1], a[s][2], a[s][3],
                    aBase + (uint32_t)s * (16u * RB) + aoff + (uint32_t)ks * 32u);
        u64 nxt[4];
        if (ks < 7) {
#pragma unroll
            for (int j = 0; j < 4; j++) nxt[j] = __ldg(fb + (ks + 1) * 512 + j * 32);
        }
#pragma unroll
        for (int s = 0; s < 3; s++)
#pragma unroll
            for (int j = 0; j < 4; j++)
                mma_bf16(acc[s][j], a[s][0], a[s][1], a[s][2], a[s][3],
                         (uint32_t)cur[j], (uint32_t)(cur[j] >> 32));
        if (ks < 7) {
#pragma unroll
            for (int j = 0; j < 4; j++) cur[j] = nxt[j];
        }
    }
}

// dual-A, shared-B (static hi*hi + lo*hi)
__device__ __forceinline__ void gemm3g_dual(uint32_t aBase1, uint32_t aBase2, uint32_t aoff,
                                            const u64* __restrict__ fb,
                                            float acc[3][4][4])
{
#pragma unroll
    for (int ks = 0; ks < 8; ks++) {
        u64 cur[4];
#pragma unroll
        for (int j = 0; j < 4; j++) cur[j] = __ldg(fb + ks * 512 + j * 32);
        uint32_t a1[3][4], a2[3][4];
#pragma unroll
        for (int s = 0; s < 3; s++) {
            ldsm_x4(a1[s][0], a1[s][1], a1[s][2], a1[s][3],
                    aBase1 + (uint32_t)s * (16u * RB) + aoff + (uint32_t)ks * 32u);
            ldsm_x4(a2[s][0], a2[s][1], a2[s][2], a2[s][3],
                    aBase2 + (uint32_t)s * (16u * RB) + aoff + (uint32_t)ks * 32u);
        }
#pragma unroll
        for (int s = 0; s < 3; s++)
#pragma unroll
            for (int j = 0; j < 4; j++) {
                uint32_t b0 = (uint32_t)cur[j], b1 = (uint32_t)(cur[j] >> 32);
                mma_bf16(acc[s][j], a1[s][0], a1[s][1], a1[s][2], a1[s][3], b0, b1);
                mma_bf16(acc[s][j], a2[s][0], a2[s][1], a2[s][2], a2[s][3], b0, b1);
            }
    }
}

__device__ __forceinline__ void zero_acc(float acc[3][4][4]) {
#pragma unroll
    for (int s = 0; s < 3; s++)
#pragma unroll
        for (int j = 0; j < 4; j++)
#pragma unroll
            for (int e = 0; e < 4; e++) acc[s][j][e] = 0.f;
}

__device__ __forceinline__ void build_A(const float* __restrict__ Xs,
                                        unsigned char* __restrict__ smA, int tid)
{
#pragma unroll
    for (int i = 0; i < 24; i++) {
        int p = tid + i * NTHREADS;
        int row = p >> 6, cp = p & 63;
        float2 v = *(const float2*)(Xs + row * XSTR + 2 * cp);
        *(uint32_t*)(smA + (uint32_t)row * RB + (uint32_t)cp * 4u) = bf16x2(v.x, v.y);
    }
}

// epilogue into a 272-stride buffer (K, V)
__device__ __forceinline__ void epi_kv(const float acc[3][4][4], const float* __restrict__ bias,
                                       unsigned char* __restrict__ dst, int n0, int g, int tg)
{
#pragma unroll
    for (int s = 0; s < 3; s++) {
        int r0 = 16 * s + g;
#pragma unroll
        for (int j = 0; j < 4; j++) {
            int c = n0 + 8 * j + 2 * tg;
            float bv0 = __ldg(bias + c), bv1 = __ldg(bias + c + 1);
            *(uint32_t*)(dst + (uint32_t)r0 * RB + 2u * c) =
                bf16x2(acc[s][j][0] + bv0, acc[s][j][1] + bv1);
            *(uint32_t*)(dst + (uint32_t)(r0 + 8) * RB + 2u * c) =
                bf16x2(acc[s][j][2] + bv0, acc[s][j][3] + bv1);
        }
    }
}

// epilogue into the swizzled 256-stride Q buffer
__device__ __forceinline__ void epi_q(const float acc[3][4][4], const float* __restrict__ bias,
                                      unsigned char* __restrict__ dst, int n0, int g, int tg)
{
    const uint32_t swz = (uint32_t)(g & 7) << 5;   // rows 16s+g and +8 share (row&7)==g
#pragma unroll
    for (int s = 0; s < 3; s++) {
        int r0 = 16 * s + g;
#pragma unroll
        for (int j = 0; j < 4; j++) {
            int c = n0 + 8 * j + 2 * tg;
            float bv0 = __ldg(bias + c), bv1 = __ldg(bias + c + 1);
            uint32_t off = ((uint32_t)(2 * c)) ^ swz;
            *(uint32_t*)(dst + (uint32_t)r0 * QRB + off) =
                bf16x2(acc[s][j][0] + bv0, acc[s][j][1] + bv1);
            *(uint32_t*)(dst + (uint32_t)(r0 + 8) * QRB + off) =
                bf16x2(acc[s][j][2] + bv0, acc[s][j][3] + bv1);
        }
    }
}

// prep: pack 10 weight images into mma-fragment order (verified v7/v8).
__global__ void dango_prep(const float* __restrict__ Ws,
                           const float* __restrict__ Wq, const float* __restrict__ Wk,
                           const float* __restrict__ Wv, const float* __restrict__ Wo)
{
    int t = blockIdx.x * 256 + threadIdx.x;      // 0..40959
    int img  = t >> 12;
    int r    = t & 4095;
    int ks   = r >> 9;
    int j    = (r >> 5) & 15;
    int lane = r & 31;
    int n  = 8 * j + (lane >> 2);
    int k0 = 16 * ks + 2 * (lane & 3);

    const float* src;
    int lo = 0;
    if (img < 8) {
        int l = img >> 2, m = img & 3;
        src = (m == 0 ? Wq : m == 1 ? Wk : m == 2 ? Wv : Wo) + (size_t)l * H * H;
    } else {
        src = Ws;
        lo = (img == 9);
    }

    float w[4];
    w[0] = __ldg(src + (k0)     * H + n);
    w[1] = __ldg(src + (k0 + 1) * H + n);
    w[2] = __ldg(src + (k0 + 8) * H + n);
    w[3] = __ldg(src + (k0 + 9) * H + n);

    __nv_bfloat16 v[4];
#pragma unroll
    for (int i = 0; i < 4; i++) {
        if (!lo) v[i] = __float2bfloat16(w[i]);
        else {
            __nv_bfloat16 h = __float2bfloat16(w[i]);
            v[i] = __float2bfloat16(w[i] - __bfloat162float(h));
        }
    }
    uint32_t b0, b1;
    { __nv_bfloat162 p = __halves2bfloat162(v[0], v[1]); b0 = *(uint32_t*)&p; }
    { __nv_bfloat162 p = __halves2bfloat162(v[2], v[3]); b1 = *(uint32_t*)&p; }
    g_frag[t] = (u64)b0 | ((u64)b1 << 32);
}

__global__ __launch_bounds__(NTHREADS, 3)
void dango_mma(const float* __restrict__ X0,
               const float* __restrict__ bs_, const float* __restrict__ bq_,
               const float* __restrict__ bk_, const float* __restrict__ bv_,
               const float* __restrict__ bo_, const float* __restrict__ beta,
               const float* __restrict__ Wp, const float* __restrict__ bp,
               float* __restrict__ out)
{
    extern __shared__ unsigned char sm[];
    float*         Xs = (float*)(sm + XS_OFF);
    unsigned char* Ab = sm + AB_OFF;
    unsigned char* Kb = sm + KB_OFF;
    unsigned char* Vb = sm + VB_OFF;
    unsigned char* Qb = sm + QB_OFF;

    const int tid  = threadIdx.x;
    const int wid  = tid >> 5;
    const int lane = tid & 31;
    const int g    = lane >> 2;
    const int tg   = lane & 3;
    const int n0   = wid * 32;
    const int g0   = blockIdx.x * GPB;
    const size_t base = (size_t)g0 * SEQ * H;

    const uint32_t smbase = smem_u32(sm);
    const uint32_t aoff   = (uint32_t)(lane & 15) * RB + (uint32_t)(lane >> 4) * 16u;
    const uint32_t AbA = smbase + AB_OFF;
    const uint32_t KbA = smbase + KB_OFF, VbA = smbase + VB_OFF;
    const u64* fwarp = g_frag + wid * 128 + lane;   // + img*4096 + ks*512 + j*32

    // ---- init: Xs ----
#pragma unroll
    for (int i = 0; i < 12; i++) {
        int idx = tid + i * NTHREADS;        // 1536 float4
        int row = idx >> 5, c4 = idx & 31;
        float4 v = __ldg((const float4*)(X0 + base + (size_t)row * H + c4 * 4));
        *(float4*)(Xs + row * XSTR + c4 * 4) = v;
    }
    __syncthreads();

    float acc[3][4][4];

    // ---- attention layers ----
    for (int l = 0; l < 2; l++) {
        build_A(Xs, Ab, tid);
        __syncthreads();

        // Q, K, V back-to-back, sync-free
        zero_acc(acc);
        gemm3g(AbA, aoff, fwarp + (l * 4 + 0) * 4096, acc);
        epi_q(acc, bq_ + l * H, Qb, n0, g, tg);

        zero_acc(acc);
        gemm3g(AbA, aoff, fwarp + (l * 4 + 1) * 4096, acc);
        epi_kv(acc, bk_ + l * H, Kb, n0, g, tg);

        zero_acc(acc);
        gemm3g(AbA, aoff, fwarp + (l * 4 + 2) * 4096, acc);
        epi_kv(acc, bv_ + l * H, Vb, n0, g, tg);
        __syncthreads();

        // attention (exclude-self softmax, per-head) -> Ab
        if (tid < GPB * 4) {
            const int grp = tid >> 2, h = tid & 3;
            const int rb = grp * SEQ, ho = h * 32;
            const float inv = 0.17677669529663687f;   // 1/sqrt(32)
#pragma unroll
            for (int qi = 0; qi < SEQ; qi++) {
                const int k0 = (qi == 0) ? 1 : 0;
                const int k1 = (qi == 2) ? 1 : 2;
                const int row = rb + qi;
                const uint32_t swz = (uint32_t)(row & 7) << 5;
                const unsigned char* qrow = Qb + (uint32_t)row * QRB;
                const __nv_bfloat162* ka = (const __nv_bfloat162*)(Kb + (uint32_t)(rb + k0) * RB + 2u * ho);
                const __nv_bfloat162* kb = (const __nv_bfloat162*)(Kb + (uint32_t)(rb + k1) * RB + 2u * ho);
                float s0 = 0.f, s1 = 0.f;
#pragma unroll
                for (int d = 0; d < 16; d++) {
                    float2 qv = __bfloat1622float2(
                        *(const __nv_bfloat162*)(qrow + (((uint32_t)(64 * h + 4 * d)) ^ swz)));
                    float2 va = __bfloat1622float2(ka[d]);
                    float2 vb = __bfloat1622float2(kb[d]);
                    s0 += qv.x * va.x + qv.y * va.y;
                    s1 += qv.x * vb.x + qv.y * vb.y;
                }
                s0 *= inv; s1 *= inv;
                float mx = fmaxf(s0, s1);
                float e0 = expf(s0 - mx), e1 = expf(s1 - mx);
                float rr = 1.0f / (e0 + e1);
                float w0 = e0 * rr, w1 = e1 * rr;
                const __nv_bfloat162* v0 = (const __nv_bfloat162*)(Vb + (uint32_t)(rb + k0) * RB + 2u * ho);
                const __nv_bfloat162* v1 = (const __nv_bfloat162*)(Vb + (uint32_t)(rb + k1) * RB + 2u * ho);
#pragma unroll
                for (int d = 0; d < 16; d++) {
                    float2 a = __bfloat1622float2(v0[d]);
                    float2 b = __bfloat1622float2(v1[d]);
                    *(uint32_t*)(Ab + (uint32_t)row * RB + 2u * (ho + 2 * d)) =
                        bf16x2(w0 * a.x + w1 * b.x, w0 * a.y + w1 * b.y);
                }
            }
        }
        __syncthreads();

        // O gemm + ReZero residual into Xs
        zero_acc(acc);
        gemm3g(AbA, aoff, fwarp + (l * 4 + 3) * 4096, acc);
        {
            const float betaL = __ldg(beta + l);
            const float* bo = bo_ + l * H;
#pragma unroll
            for (int s = 0; s < 3; s++) {
                int r0 = 16 * s + g;
#pragma unroll
                for (int j = 0; j < 4; j++) {
                    int c = n0 + 8 * j + 2 * tg;
                    float bv0 = __ldg(bo + c), bv1 = __ldg(bo + c + 1);
                    float2* p0 = (float2*)(Xs + r0 * XSTR + c);
                    float2* p1 = (float2*)(Xs + (r0 + 8) * XSTR + c);
                    float2 x0 = *p0, x1 = *p1;
                    x0.x += betaL * (acc[s][j][0] + bv0);
                    x0.y += betaL * (acc[s][j][1] + bv1);
                    x1.x += betaL * (acc[s][j][2] + bv0);
                    x1.y += betaL * (acc[s][j][3] + bv1);
                    *p0 = x0; *p1 = x1;
                }
            }
        }
        __syncthreads();
    }

    // ---- static path: relu(X0 @ Ws + bs), hi/lo split ----
#pragma unroll
    for (int i = 0; i < 24; i++) {
        int p = tid + i * NTHREADS;
        int row = p >> 6, cp = p & 63;
        float2 v = __ldg((const float2*)(X0 + base + (size_t)row * H + 2 * cp));
        __nv_bfloat16 h0 = __float2bfloat16(v.x), h1 = __float2bfloat16(v.y);
        float r0 = v.x - __bfloat162float(h0), r1 = v.y - __bfloat162float(h1);
        uint32_t off = (uint32_t)row * RB + (uint32_t)cp * 4u;
        __nv_bfloat162 hv = __halves2bfloat162(h0, h1);
        *(uint32_t*)(Kb + off) = *(uint32_t*)&hv;       // A_hi
        *(uint32_t*)(Vb + off) = bf16x2(r0, r1);        // A_lo
    }
    __syncthreads();

    zero_acc(acc);
    gemm3g_dual(KbA, VbA, aoff, fwarp + 8 * 4096, acc);   // hi*hi + lo*hi
    gemm3g(KbA, aoff, fwarp + 9 * 4096, acc);             // hi*lo

    // score: per-thread partials (reads Xs), then overlay sSc on Xs
    float pr[3][2];
#pragma unroll
    for (int s = 0; s < 3; s++) {
        int r0 = 16 * s + g;
        float sa = 0.f, sb2 = 0.f;
#pragma unroll
        for (int j = 0; j < 4; j++) {
            int c = n0 + 8 * j + 2 * tg;
            float w0 = __ldg(Wp + c), w1 = __ldg(Wp + c + 1);
            float b0 = __ldg(bs_ + c), b1 = __ldg(bs_ + c + 1);
            float st, d;
            st = fmaxf(acc[s][j][0] + b0, 0.f); d = Xs[r0 * XSTR + c] - st;           sa  += d * d * w0;
            st = fmaxf(acc[s][j][1] + b1, 0.f); d = Xs[r0 * XSTR + c + 1] - st;       sa  += d * d * w1;
            st = fmaxf(acc[s][j][2] + b0, 0.f); d = Xs[(r0 + 8) * XSTR + c] - st;     sb2 += d * d * w0;
            st = fmaxf(acc[s][j][3] + b1, 0.f); d = Xs[(r0 + 8) * XSTR + c + 1] - st; sb2 += d * d * w1;
        }
        sa  += __shfl_xor_sync(0xffffffffu, sa, 1);
        sa  += __shfl_xor_sync(0xffffffffu, sa, 2);
        sb2 += __shfl_xor_sync(0xffffffffu, sb2, 1);
        sb2 += __shfl_xor_sync(0xffffffffu, sb2, 2);
        pr[s][0] = sa; pr[s][1] = sb2;
    }
    __syncthreads();                       // all Xs reads done

    float* sSc = Xs;                       // reuse Xs[0..47]
    if (tid < TPB) sSc[tid] = __ldg(bp);
    __syncthreads();
    if (tg == 0) {
#pragma unroll
        for (int s = 0; s < 3; s++) {
            atomicAdd(&sSc[16 * s + g],     pr[s][0]);
            atomicAdd(&sSc[16 * s + g + 8], pr[s][1]);
        }
    }
    __syncthreads();

    if (tid < GPB)
        out[g0 + tid] = (sSc[tid * 3] + sSc[tid * 3 + 1] + sSc[tid * 3 + 2]) * (1.0f / 3.0f);
}

extern "C" void kernel_launch(void* const* d_in, const int* in_sizes, int n_in,
                              void* d_out, int out_size)
{
    const float* X0  = (const float*)d_in[0];
    // d_in[1] = batch (int64) — implicit: repeat(arange(G), 3)
    const float* Ws  = (const float*)d_in[2];
    const float* bs  = (const float*)d_in[3];
    const float* Wq  = (const float*)d_in[4];
    const float* bq  = (const float*)d_in[5];
    const float* Wk  = (const float*)d_in[6];
    const float* bk  = (const float*)d_in[7];
    const float* Wv  = (const float*)d_in[8];
    const float* bv  = (const float*)d_in[9];
    const float* Wo  = (const float*)d_in[10];
    const float* bo  = (const float*)d_in[11];
    const float* bet = (const float*)d_in[12];
    const float* Wp  = (const float*)d_in[13];
    const float* bp  = (const float*)d_in[14];
    float* out = (float*)d_out;

    dango_prep<<<160, 256>>>(Ws, Wq, Wk, Wv, Wo);

    cudaFuncSetAttribute(dango_mma, cudaFuncAttributeMaxDynamicSharedMemorySize, SMEM_SZ);
    dango_mma<<<GROUPS / GPB, NTHREADS, SMEM_SZ>>>(
        X0, bs, bq, bk, bv, bo, bet, Wp, bp, out);
}